// round 6
// baseline (speedup 1.0000x reference)
#include <cuda_runtime.h>

// Problem constants
#define SRC_HW   64
#define CELLS    4096        // 64*64 flow cells per batch-slice
#define CH       256
#define NB       4           // output batches
#define NN       4           // accumulated slices (num)
#define HO       192         // output H = W = 3*64
#define NBB      16          // NB*NN batch-slices
#define PW       72          // padded plane width/height (4 zero border each side)

#define REP_F4   1300        // float4 stride per replica (5200 words >= 5184+tail)
#define SMEM_F4  (4 * REP_F4)
#define SMEM_BYTES (SMEM_F4 * 16)

// Precomputed per-(bb, cell) metadata:
//  .x = bitcast int: SMEM word offset of patch base in padded 72x72 plane
//  .y = m * (1 - ay)
//  .z = m * ay
//  .w = ax
__device__ float4 g_meta[NBB * CELLS];   // 1 MB static scratch

__global__ void meta_kernel(const float* __restrict__ flow,
                            const float* __restrict__ masks) {
    int idx = blockIdx.x * blockDim.x + threadIdx.x;
    if (idx >= NBB * CELLS) return;
    int bb   = idx >> 12;
    int cell = idx & (CELLS - 1);
    int cy = cell >> 6;
    int cx = cell & 63;

    float fy = flow[((size_t)(bb * 2 + 0)) * CELLS + cell];
    float fx = flow[((size_t)(bb * 2 + 1)) * CELLS + cell];
    float m  = masks[(size_t)bb * CELLS + cell];

    float by = (float)cy + fy;
    float bx = (float)cx + fx;
    float y0f = floorf(by);
    float x0f = floorf(bx);
    float ay = by - y0f;
    float ax = bx - x0f;
    int y0 = (int)y0f;
    int x0 = (int)x0f;

    int yb = min(max(y0 - 1, -4), SRC_HW);
    int xb = min(max(x0 - 1, -4), SRC_HW);
    int off = (yb + 4) * PW + (xb + 4);

    g_meta[idx] = make_float4(__int_as_float(off), m * (1.0f - ay), m * ay, ax);
}

// One 512-thread CTA per (channel, batch). Padded plane stored 4x in SMEM with
// word shifts 0..3 so any 4-consecutive-word patch row is one aligned LDS.128.
__global__ __launch_bounds__(512, 1)
void extract_kernel(const float* __restrict__ src, float* __restrict__ out) {
    const int c = blockIdx.x;   // 0..255
    const int b = blockIdx.y;   // 0..3
    const int t = threadIdx.x;  // 0..511

    extern __shared__ float4 smem4[];   // [4][REP_F4]; replica r word i = plane[i+r]

    // Zero everything once: borders + tails stay zero forever.
    float4 z4 = make_float4(0.f, 0.f, 0.f, 0.f);
    for (int i = t; i < SMEM_F4; i += 512) smem4[i] = z4;

    float acc[8][9];
#pragma unroll
    for (int j = 0; j < 8; j++)
#pragma unroll
        for (int q = 0; q < 9; q++) acc[j][q] = 0.0f;

    for (int n = 0; n < NN; n++) {
        __syncthreads();   // previous gather (or zero-fill) done before overwrite
        const int bb = n * NB + b;

        // Step A: load 64x64 plane into padded interior of replica 0.
        // Interior float4 slots are 16B-aligned: (row+4)*72 + 4 + 4*col4 ≡ 0 mod 4.
        const float4* sp = (const float4*)(src + ((size_t)(bb * CH + c)) * CELLS);
#pragma unroll
        for (int k = 0; k < 2; k++) {
            int i    = t + 512 * k;    // float4 index 0..1023
            int row  = i >> 4;         // 16 float4 per source row
            int col4 = i & 15;
            smem4[((row + 4) * PW + 4 + col4 * 4) >> 2] = sp[i];
        }
        __syncthreads();

        // Step B: build shifted replicas 1..3 from replica 0.
        // Nonzero plane words live in [292, 4892) -> f4 indices [72, 1224).
        for (int k = 72 + t; k < 1224; k += 512) {
            float4 a = smem4[k];
            float4 bv = smem4[k + 1];
            smem4[REP_F4     + k] = make_float4(a.y, a.z, a.w, bv.x);
            smem4[2 * REP_F4 + k] = make_float4(a.z, a.w, bv.x, bv.y);
            smem4[3 * REP_F4 + k] = make_float4(a.w, bv.x, bv.y, bv.z);
        }
        __syncthreads();

        const float4* __restrict__ metaB = g_meta + (size_t)bb * CELLS;

#pragma unroll
        for (int j = 0; j < 8; j++) {
            float4 mt = metaB[t + 512 * j];
            int off = __float_as_int(mt.x);
            int r   = off & 3;
            const float4* __restrict__ p4 = smem4 + r * REP_F4 + ((off - r) >> 2);
            float wv0 = mt.y, wv1 = mt.z, ax = mt.w;

            // 4x4 patch: one aligned LDS.128 per row (PW/4 = 18 f4 row stride)
            float4 v0 = p4[0];
            float4 v1 = p4[18];
            float4 v2 = p4[36];
            float4 v3 = p4[54];

            // Horizontal lerps (3 per row), then masked vertical FMAs
            float h0[3], h1[3], h2[3], h3[3];
            h0[0] = fmaf(ax, v0.y - v0.x, v0.x);
            h0[1] = fmaf(ax, v0.z - v0.y, v0.y);
            h0[2] = fmaf(ax, v0.w - v0.z, v0.z);
            h1[0] = fmaf(ax, v1.y - v1.x, v1.x);
            h1[1] = fmaf(ax, v1.z - v1.y, v1.y);
            h1[2] = fmaf(ax, v1.w - v1.z, v1.z);
            h2[0] = fmaf(ax, v2.y - v2.x, v2.x);
            h2[1] = fmaf(ax, v2.z - v2.y, v2.y);
            h2[2] = fmaf(ax, v2.w - v2.z, v2.z);
            h3[0] = fmaf(ax, v3.y - v3.x, v3.x);
            h3[1] = fmaf(ax, v3.z - v3.y, v3.y);
            h3[2] = fmaf(ax, v3.w - v3.z, v3.z);

#pragma unroll
            for (int q = 0; q < 3; q++) {
                acc[j][0 + q] = fmaf(wv1, h1[q], fmaf(wv0, h0[q], acc[j][0 + q]));
                acc[j][3 + q] = fmaf(wv1, h2[q], fmaf(wv0, h1[q], acc[j][3 + q]));
                acc[j][6 + q] = fmaf(wv1, h3[q], fmaf(wv0, h2[q], acc[j][6 + q]));
            }
        }
    }

    // Write 8 cells x 3x3 outputs
    float* ob = out + ((size_t)(b * CH + c)) * (HO * HO);
#pragma unroll
    for (int j = 0; j < 8; j++) {
        int cell = t + 512 * j;
        int cy = cell >> 6;
        int cx = cell & 63;
#pragma unroll
        for (int i = 0; i < 3; i++) {
            float* row = ob + (size_t)(cy * 3 + i) * HO + cx * 3;
            row[0] = acc[j][i * 3 + 0];
            row[1] = acc[j][i * 3 + 1];
            row[2] = acc[j][i * 3 + 2];
        }
    }
}

extern "C" void kernel_launch(void* const* d_in, const int* in_sizes, int n_in,
                              void* d_out, int out_size) {
    const float* src   = (const float*)d_in[0];  // (16, 256, 64, 64)
    const float* flow  = (const float*)d_in[1];  // (16, 2, 64, 64)
    const float* masks = (const float*)d_in[2];  // (16, 1, 64, 64)
    float* out = (float*)d_out;                  // (4, 256, 192, 192)

    static int attr_done = 0;
    if (!attr_done) {
        cudaFuncSetAttribute(extract_kernel,
                             cudaFuncAttributeMaxDynamicSharedMemorySize,
                             SMEM_BYTES);
        attr_done = 1;
    }

    meta_kernel<<<(NBB * CELLS + 255) / 256, 256>>>(flow, masks);

    dim3 grid(CH, NB);
    extract_kernel<<<grid, 512, SMEM_BYTES>>>(src, out);
}

// round 7
// speedup vs baseline: 1.1569x; 1.1569x over previous
#include <cuda_runtime.h>
#include <cuda_fp16.h>

// Problem constants
#define SRC_HW   64
#define CELLS    4096        // 64*64 flow cells per batch-slice
#define CH       256
#define NB       4           // output batches
#define NN       4           // accumulated slices (num)
#define HO       192         // output H = W = 3*64
#define NBB      16          // NB*NN batch-slices
#define PW       72          // padded plane width/height (4 zero border each side)
#define RW       36          // half2 words per padded row
#define REPW     (PW * RW)   // half2 words per parity replica (2592)

// Precomputed per-(bb, cell) metadata:
//  .x = bitcast int: BYTE offset of patch-row base into the half2 replica pair
//       (parity*REPW + py*RW + (px>>1)) * 4, py/px = clamped padded base coords
//  .y = m * (1 - ay)
//  .z = m * ay
//  .w = ax
__device__ float4 g_meta[NBB * CELLS];   // 1 MB static scratch

__global__ void meta_kernel(const float* __restrict__ flow,
                            const float* __restrict__ masks) {
    int idx = blockIdx.x * blockDim.x + threadIdx.x;
    if (idx >= NBB * CELLS) return;
    int bb   = idx >> 12;
    int cell = idx & (CELLS - 1);
    int cy = cell >> 6;
    int cx = cell & 63;

    float fy = flow[((size_t)(bb * 2 + 0)) * CELLS + cell];
    float fx = flow[((size_t)(bb * 2 + 1)) * CELLS + cell];
    float m  = masks[(size_t)bb * CELLS + cell];

    float by = (float)cy + fy;
    float bx = (float)cx + fx;
    float y0f = floorf(by);
    float x0f = floorf(bx);
    float ay = by - y0f;
    float ax = bx - x0f;
    int y0 = (int)y0f;
    int x0 = (int)x0f;

    // Clamp patch base into the padded plane (zero borders give exact
    // zero-outside bilinear semantics).
    int yb = min(max(y0 - 1, -4), SRC_HW);
    int xb = min(max(x0 - 1, -4), SRC_HW);
    int py = yb + 4;                  // 0..68
    int px = xb + 4;                  // 0..68
    int parity = px & 1;
    int word   = px >> 1;             // 0..34
    int mo = (parity * REPW + py * RW + word) * 4;   // byte offset

    g_meta[idx] = make_float4(__int_as_float(mo), m * (1.0f - ay), m * ay, ax);
}

// One block per (channel, batch, cell-quarter). Source plane staged fp32,
// then packed to fp16 half2 in two x-parity replicas so a 4-tap patch row is
// 2 LDS.32 (2 bank touches) instead of 4 — halves the shared-memory
// wavefront bound.
__global__ __launch_bounds__(256, 3)
void extract_kernel(const float* __restrict__ src, float* __restrict__ out) {
    const int c = blockIdx.x;   // 0..255
    const int b = blockIdx.y;   // 0..3
    const int z = blockIdx.z;   // 0..3  (cell quarter)
    const int t = threadIdx.x;  // 0..255

    __shared__ float  plane_f[PW * PW];     // 20736 B fp32 staging
    __shared__ __half2 rep[2 * REPW];       // 20736 B packed fp16 replicas

    // Zero the fp32 staging once; borders stay zero, interior overwritten
    // each plane. (Replicas are fully rebuilt from plane_f every n.)
    for (int i = t; i < PW * PW; i += 256) plane_f[i] = 0.0f;

    float acc[4][9];
#pragma unroll
    for (int j = 0; j < 4; j++)
#pragma unroll
        for (int q = 0; q < 9; q++) acc[j][q] = 0.0f;

    const int cell0 = z * 1024;

    for (int n = 0; n < NN; n++) {
        __syncthreads();   // previous compute done before overwrite
        const int bb = n * NB + b;

        // Stage fp32 plane into padded interior (STS.128)
        const float4* sp = (const float4*)(src + ((size_t)(bb * CH + c)) * CELLS);
#pragma unroll
        for (int k = 0; k < 4; k++) {
            int i    = t + 256 * k;    // float4 index 0..1023
            int row  = i >> 4;         // 16 float4 per source row
            int col4 = i & 15;
            float4 v = sp[i];
            *(float4*)&plane_f[(row + 4) * PW + 4 + col4 * 4] = v;
        }
        __syncthreads();

        // Build both parity replicas: rep0[row][j]=(f[2j],f[2j+1]),
        // rep1[row][j]=(f[2j+1],f[2j+2]).
        for (int i = t; i < REPW; i += 256) {
            int row = i / RW;
            int j   = i - row * RW;
            const float* f = plane_f + row * PW + 2 * j;
            float a0 = f[0];
            float a1 = f[1];
            float a2 = (j < RW - 1) ? f[2] : 0.0f;
            rep[i]        = __floats2half2_rn(a0, a1);
            rep[REPW + i] = __floats2half2_rn(a1, a2);
        }
        __syncthreads();

        const float4* __restrict__ metaB = g_meta + (size_t)bb * CELLS + cell0;

#pragma unroll
        for (int j = 0; j < 4; j++) {
            float4 mt = metaB[t + 256 * j];
            const __half2* __restrict__ p =
                (const __half2*)((const char*)rep + __float_as_int(mt.x));
            float wv0 = mt.y, wv1 = mt.z, ax = mt.w;

            // 4x4 patch: 2 LDS.32 per row, parity-uniform extraction
            float2 r0a = __half22float2(p[0]);
            float2 r0b = __half22float2(p[1]);
            float2 r1a = __half22float2(p[RW]);
            float2 r1b = __half22float2(p[RW + 1]);
            float2 r2a = __half22float2(p[2 * RW]);
            float2 r2b = __half22float2(p[2 * RW + 1]);
            float2 r3a = __half22float2(p[3 * RW]);
            float2 r3b = __half22float2(p[3 * RW + 1]);

            // Horizontal lerps (v0..v3 = a.x, a.y, b.x, b.y)
            float h0[3], h1[3], h2[3], h3[3];
            h0[0] = fmaf(ax, r0a.y - r0a.x, r0a.x);
            h0[1] = fmaf(ax, r0b.x - r0a.y, r0a.y);
            h0[2] = fmaf(ax, r0b.y - r0b.x, r0b.x);
            h1[0] = fmaf(ax, r1a.y - r1a.x, r1a.x);
            h1[1] = fmaf(ax, r1b.x - r1a.y, r1a.y);
            h1[2] = fmaf(ax, r1b.y - r1b.x, r1b.x);
            h2[0] = fmaf(ax, r2a.y - r2a.x, r2a.x);
            h2[1] = fmaf(ax, r2b.x - r2a.y, r2a.y);
            h2[2] = fmaf(ax, r2b.y - r2b.x, r2b.x);
            h3[0] = fmaf(ax, r3a.y - r3a.x, r3a.x);
            h3[1] = fmaf(ax, r3b.x - r3a.y, r3a.y);
            h3[2] = fmaf(ax, r3b.y - r3b.x, r3b.x);

            // Masked vertical FMAs
#pragma unroll
            for (int q = 0; q < 3; q++) {
                acc[j][0 + q] = fmaf(wv1, h1[q], fmaf(wv0, h0[q], acc[j][0 + q]));
                acc[j][3 + q] = fmaf(wv1, h2[q], fmaf(wv0, h1[q], acc[j][3 + q]));
                acc[j][6 + q] = fmaf(wv1, h3[q], fmaf(wv0, h2[q], acc[j][6 + q]));
            }
        }
    }

    // Write 4 cells x 3x3 outputs (adjacent threads -> adjacent 3-float groups)
    float* ob = out + ((size_t)(b * CH + c)) * (HO * HO);
#pragma unroll
    for (int j = 0; j < 4; j++) {
        int cell = cell0 + t + 256 * j;
        int cy = cell >> 6;
        int cx = cell & 63;
#pragma unroll
        for (int i = 0; i < 3; i++) {
            float* row = ob + (size_t)(cy * 3 + i) * HO + cx * 3;
            row[0] = acc[j][i * 3 + 0];
            row[1] = acc[j][i * 3 + 1];
            row[2] = acc[j][i * 3 + 2];
        }
    }
}

extern "C" void kernel_launch(void* const* d_in, const int* in_sizes, int n_in,
                              void* d_out, int out_size) {
    const float* src   = (const float*)d_in[0];  // (16, 256, 64, 64)
    const float* flow  = (const float*)d_in[1];  // (16, 2, 64, 64)
    const float* masks = (const float*)d_in[2];  // (16, 1, 64, 64)
    float* out = (float*)d_out;                  // (4, 256, 192, 192)

    meta_kernel<<<(NBB * CELLS + 255) / 256, 256>>>(flow, masks);

    dim3 grid(CH, NB, 4);
    extract_kernel<<<grid, 256>>>(src, out);
}

// round 8
// speedup vs baseline: 1.2152x; 1.0504x over previous
#include <cuda_runtime.h>
#include <cuda_fp16.h>

// Problem constants
#define SRC_HW   64
#define CELLS    4096        // 64*64 flow cells per batch-slice
#define CH       256
#define NB       4           // output batches
#define NN       4           // accumulated slices (num)
#define HO       192         // output H = W = 3*64
#define NBB      16          // NB*NN batch-slices
#define PW       72          // padded plane width/height (4 zero border each side)
#define RW       36          // half2 words per padded row
#define REPW     (PW * RW)   // half2 words per parity replica (2592)
#define NPLANES  (NBB * CH)

// fp16 padded planes, packed 2-per-word (borders zero). 42.5 MB static.
__device__ __half2 g_packed[(size_t)NPLANES * REPW];

// Precomputed per-(bb, cell) metadata:
//  .x = bitcast int: BYTE offset of patch-row base into the half2 replica pair
//       (parity*REPW + py*RW + (px>>1)) * 4
//  .y = m * (1 - ay)
//  .z = m * ay
//  .w = ax
__device__ float4 g_meta[NBB * CELLS];   // 1 MB static scratch

__global__ void pack_kernel(const float* __restrict__ src) {
    int idx = blockIdx.x * blockDim.x + threadIdx.x;
    if (idx >= NPLANES * REPW) return;
    int plane = idx / REPW;
    int w     = idx - plane * REPW;
    int row   = w / RW;
    int j     = w - row * RW;

    int sy = row - 4;
    int sx = 2 * j - 4;
    float a = 0.0f, b = 0.0f;
    if ((unsigned)sy < (unsigned)SRC_HW) {
        const float* sr = src + (size_t)plane * CELLS + sy * SRC_HW;
        if ((unsigned)sx < (unsigned)SRC_HW)       a = sr[sx];
        if ((unsigned)(sx + 1) < (unsigned)SRC_HW) b = sr[sx + 1];
    }
    g_packed[idx] = __floats2half2_rn(a, b);
}

__global__ void meta_kernel(const float* __restrict__ flow,
                            const float* __restrict__ masks) {
    int idx = blockIdx.x * blockDim.x + threadIdx.x;
    if (idx >= NBB * CELLS) return;
    int bb   = idx >> 12;
    int cell = idx & (CELLS - 1);
    int cy = cell >> 6;
    int cx = cell & 63;

    float fy = flow[((size_t)(bb * 2 + 0)) * CELLS + cell];
    float fx = flow[((size_t)(bb * 2 + 1)) * CELLS + cell];
    float m  = masks[(size_t)bb * CELLS + cell];

    float by = (float)cy + fy;
    float bx = (float)cx + fx;
    float y0f = floorf(by);
    float x0f = floorf(bx);
    float ay = by - y0f;
    float ax = bx - x0f;
    int y0 = (int)y0f;
    int x0 = (int)x0f;

    int yb = min(max(y0 - 1, -4), SRC_HW);
    int xb = min(max(x0 - 1, -4), SRC_HW);
    int py = yb + 4;                  // 0..68
    int px = xb + 4;                  // 0..68
    int parity = px & 1;
    int word   = px >> 1;             // 0..34
    int mo = (parity * REPW + py * RW + word) * 4;   // byte offset

    g_meta[idx] = make_float4(__int_as_float(mo), m * (1.0f - ay), m * ay, ax);
}

// One block per (channel, batch, cell-quarter). Prepacked fp16 plane copied
// GMEM->SMEM as replica 0; replica 1 (x-shifted by one half) built with
// funnel shifts. Patch rows are 2 LDS.32 from the parity-matched replica.
__global__ __launch_bounds__(256, 3)
void extract_kernel(float* __restrict__ out) {
    const int c = blockIdx.x;   // 0..255
    const int b = blockIdx.y;   // 0..3
    const int z = blockIdx.z;   // 0..3  (cell quarter)
    const int t = threadIdx.x;  // 0..255

    __shared__ __half2 rep[2 * REPW];   // 20736 B

    float acc[4][9];
#pragma unroll
    for (int j = 0; j < 4; j++)
#pragma unroll
        for (int q = 0; q < 9; q++) acc[j][q] = 0.0f;

    const int cell0 = z * 1024;

    for (int n = 0; n < NN; n++) {
        if (n) __syncthreads();   // previous gather done before overwrite
        const int bb = n * NB + b;

        // Fill replica 0: straight float4 copy of the prepacked plane.
        const float4* gp = (const float4*)(g_packed + (size_t)(bb * CH + c) * REPW);
        float4* r0 = (float4*)rep;
        {
            int i0 = t;          // 648 float4 total
            int i1 = t + 256;
            int i2 = t + 512;
            r0[i0] = gp[i0];
            r0[i1] = gp[i1];
            if (i2 < REPW / 2) r0[i2] = gp[i2];
        }
        __syncthreads();

        // Build replica 1: word i = (plane[2i+1], plane[2i+2]) via funnel shift.
        {
            unsigned* w = (unsigned*)rep;
            for (int i = t; i < REPW; i += 256) {
                unsigned a  = w[i];
                unsigned b2 = (i + 1 < REPW) ? w[i + 1] : 0u;
                w[REPW + i] = (a >> 16) | (b2 << 16);
            }
        }
        __syncthreads();

        const float4* __restrict__ metaB = g_meta + (size_t)bb * CELLS + cell0;

#pragma unroll
        for (int j = 0; j < 4; j++) {
            float4 mt = metaB[t + 256 * j];
            const __half2* __restrict__ p =
                (const __half2*)((const char*)rep + __float_as_int(mt.x));
            float wv0 = mt.y, wv1 = mt.z, ax = mt.w;

            // 4x4 patch: 2 LDS.32 per row
            float2 r0a = __half22float2(p[0]);
            float2 r0b = __half22float2(p[1]);
            float2 r1a = __half22float2(p[RW]);
            float2 r1b = __half22float2(p[RW + 1]);
            float2 r2a = __half22float2(p[2 * RW]);
            float2 r2b = __half22float2(p[2 * RW + 1]);
            float2 r3a = __half22float2(p[3 * RW]);
            float2 r3b = __half22float2(p[3 * RW + 1]);

            // Horizontal lerps (v0..v3 = a.x, a.y, b.x, b.y)
            float h0[3], h1[3], h2[3], h3[3];
            h0[0] = fmaf(ax, r0a.y - r0a.x, r0a.x);
            h0[1] = fmaf(ax, r0b.x - r0a.y, r0a.y);
            h0[2] = fmaf(ax, r0b.y - r0b.x, r0b.x);
            h1[0] = fmaf(ax, r1a.y - r1a.x, r1a.x);
            h1[1] = fmaf(ax, r1b.x - r1a.y, r1a.y);
            h1[2] = fmaf(ax, r1b.y - r1b.x, r1b.x);
            h2[0] = fmaf(ax, r2a.y - r2a.x, r2a.x);
            h2[1] = fmaf(ax, r2b.x - r2a.y, r2a.y);
            h2[2] = fmaf(ax, r2b.y - r2b.x, r2b.x);
            h3[0] = fmaf(ax, r3a.y - r3a.x, r3a.x);
            h3[1] = fmaf(ax, r3b.x - r3a.y, r3a.y);
            h3[2] = fmaf(ax, r3b.y - r3b.x, r3b.x);

            // Masked vertical FMAs
#pragma unroll
            for (int q = 0; q < 3; q++) {
                acc[j][0 + q] = fmaf(wv1, h1[q], fmaf(wv0, h0[q], acc[j][0 + q]));
                acc[j][3 + q] = fmaf(wv1, h2[q], fmaf(wv0, h1[q], acc[j][3 + q]));
                acc[j][6 + q] = fmaf(wv1, h3[q], fmaf(wv0, h2[q], acc[j][6 + q]));
            }
        }
    }

    // Write 4 cells x 3x3 outputs (adjacent threads -> adjacent 3-float groups)
    float* ob = out + ((size_t)(b * CH + c)) * (HO * HO);
#pragma unroll
    for (int j = 0; j < 4; j++) {
        int cell = cell0 + t + 256 * j;
        int cy = cell >> 6;
        int cx = cell & 63;
#pragma unroll
        for (int i = 0; i < 3; i++) {
            float* row = ob + (size_t)(cy * 3 + i) * HO + cx * 3;
            row[0] = acc[j][i * 3 + 0];
            row[1] = acc[j][i * 3 + 1];
            row[2] = acc[j][i * 3 + 2];
        }
    }
}

extern "C" void kernel_launch(void* const* d_in, const int* in_sizes, int n_in,
                              void* d_out, int out_size) {
    const float* src   = (const float*)d_in[0];  // (16, 256, 64, 64)
    const float* flow  = (const float*)d_in[1];  // (16, 2, 64, 64)
    const float* masks = (const float*)d_in[2];  // (16, 1, 64, 64)
    float* out = (float*)d_out;                  // (4, 256, 192, 192)

    pack_kernel<<<(NPLANES * REPW + 255) / 256, 256>>>(src);
    meta_kernel<<<(NBB * CELLS + 255) / 256, 256>>>(flow, masks);

    dim3 grid(CH, NB, 4);
    extract_kernel<<<grid, 256>>>(out);
}

// round 9
// speedup vs baseline: 1.4864x; 1.2232x over previous
#include <cuda_runtime.h>
#include <cuda_fp16.h>

// Problem constants
#define SRC_HW   64
#define CELLS    4096        // 64*64 flow cells per batch-slice
#define CH       256
#define NB       4           // output batches
#define NN       4           // accumulated slices (num)
#define HO       192         // output H = W = 3*64
#define NBB      16          // NB*NN batch-slices
#define PW       72          // padded plane width/height (4 zero border each side)
#define RW       36          // half2 words per padded row
#define REPW     (PW * RW)   // half2 words per parity replica (2592)

// Precomputed per-(bb, cell) metadata:
//  .x = bitcast int: BYTE offset of patch-row base into the half2 replica pair
//       (parity*REPW + py*RW + (px>>1)) * 4
//  .y = m * (1 - ay)
//  .z = m * ay
//  .w = ax
__device__ float4 g_meta[NBB * CELLS];   // 1 MB static scratch

__global__ void meta_kernel(const float* __restrict__ flow,
                            const float* __restrict__ masks) {
    int idx = blockIdx.x * blockDim.x + threadIdx.x;
    if (idx >= NBB * CELLS) return;
    int bb   = idx >> 12;
    int cell = idx & (CELLS - 1);
    int cy = cell >> 6;
    int cx = cell & 63;

    float fy = flow[((size_t)(bb * 2 + 0)) * CELLS + cell];
    float fx = flow[((size_t)(bb * 2 + 1)) * CELLS + cell];
    float m  = masks[(size_t)bb * CELLS + cell];

    float by = (float)cy + fy;
    float bx = (float)cx + fx;
    float y0f = floorf(by);
    float x0f = floorf(bx);
    float ay = by - y0f;
    float ax = bx - x0f;
    int y0 = (int)y0f;
    int x0 = (int)x0f;

    int yb = min(max(y0 - 1, -4), SRC_HW);
    int xb = min(max(x0 - 1, -4), SRC_HW);
    int py = yb + 4;                  // 0..68
    int px = xb + 4;                  // 0..68
    int parity = px & 1;
    int word   = px >> 1;             // 0..34
    int mo = (parity * REPW + py * RW + word) * 4;   // byte offset

    g_meta[idx] = make_float4(__int_as_float(mo), m * (1.0f - ay), m * ay, ax);
}

// One block per (channel, batch, cell-quarter). Source plane LDG'd as fp32,
// converted to packed fp16 in registers, STS'd straight into the padded
// replica-0 interior (no staging). Replica 1 (x-shifted one half) built with
// funnel shifts. Patch rows are 2 LDS.32 from the parity-matched replica.
__global__ __launch_bounds__(256, 3)
void extract_kernel(const float* __restrict__ src, float* __restrict__ out) {
    const int c = blockIdx.x;   // 0..255
    const int b = blockIdx.y;   // 0..3
    const int z = blockIdx.z;   // 0..3  (cell quarter)
    const int t = threadIdx.x;  // 0..255

    __shared__ __half2 rep[2 * REPW];   // 20736 B

    // Zero everything once (borders stay zero; interiors overwritten per n).
    {
        float4 z4 = make_float4(0.f, 0.f, 0.f, 0.f);
        float4* rz = (float4*)rep;
        for (int i = t; i < (2 * REPW) / 4; i += 256) rz[i] = z4;
    }

    float acc[4][9];
#pragma unroll
    for (int j = 0; j < 4; j++)
#pragma unroll
        for (int q = 0; q < 9; q++) acc[j][q] = 0.0f;

    const int cell0 = z * 1024;

    for (int n = 0; n < NN; n++) {
        __syncthreads();   // previous gather (or zeroing) done before overwrite
        const int bb = n * NB + b;

        // Fill replica 0 interior: LDG.128 fp32 -> 2x F2FP -> STS.64
        const float4* sp = (const float4*)(src + ((size_t)(bb * CH + c)) * CELLS);
#pragma unroll
        for (int k = 0; k < 4; k++) {
            int i    = t + 256 * k;    // float4 index 0..1023
            int row  = i >> 4;         // 16 float4 per source row
            int col4 = i & 15;
            float4 v = sp[i];
            union { __half2 h[2]; float2 f; } u;
            u.h[0] = __floats2half2_rn(v.x, v.y);
            u.h[1] = __floats2half2_rn(v.z, v.w);
            // padded word index: (row+4)*RW + (4 + 4*col4)/2  (even -> 8B aligned)
            *(float2*)(rep + (row + 4) * RW + 2 + col4 * 2) = u.f;
        }
        __syncthreads();

        // Build replica 1: word i = (plane[2i+1], plane[2i+2]) via funnel shift.
        {
            unsigned* w = (unsigned*)rep;
            for (int i = t; i < REPW; i += 256) {
                unsigned a  = w[i];
                unsigned b2 = (i + 1 < REPW) ? w[i + 1] : 0u;
                w[REPW + i] = (a >> 16) | (b2 << 16);
            }
        }
        __syncthreads();

        const float4* __restrict__ metaB = g_meta + (size_t)bb * CELLS + cell0;

#pragma unroll
        for (int j = 0; j < 4; j++) {
            float4 mt = metaB[t + 256 * j];
            const __half2* __restrict__ p =
                (const __half2*)((const char*)rep + __float_as_int(mt.x));
            float wv0 = mt.y, wv1 = mt.z, ax = mt.w;

            // 4x4 patch: 2 LDS.32 per row
            float2 r0a = __half22float2(p[0]);
            float2 r0b = __half22float2(p[1]);
            float2 r1a = __half22float2(p[RW]);
            float2 r1b = __half22float2(p[RW + 1]);
            float2 r2a = __half22float2(p[2 * RW]);
            float2 r2b = __half22float2(p[2 * RW + 1]);
            float2 r3a = __half22float2(p[3 * RW]);
            float2 r3b = __half22float2(p[3 * RW + 1]);

            // Horizontal lerps (v0..v3 = a.x, a.y, b.x, b.y)
            float h0[3], h1[3], h2[3], h3[3];
            h0[0] = fmaf(ax, r0a.y - r0a.x, r0a.x);
            h0[1] = fmaf(ax, r0b.x - r0a.y, r0a.y);
            h0[2] = fmaf(ax, r0b.y - r0b.x, r0b.x);
            h1[0] = fmaf(ax, r1a.y - r1a.x, r1a.x);
            h1[1] = fmaf(ax, r1b.x - r1a.y, r1a.y);
            h1[2] = fmaf(ax, r1b.y - r1b.x, r1b.x);
            h2[0] = fmaf(ax, r2a.y - r2a.x, r2a.x);
            h2[1] = fmaf(ax, r2b.x - r2a.y, r2a.y);
            h2[2] = fmaf(ax, r2b.y - r2b.x, r2b.x);
            h3[0] = fmaf(ax, r3a.y - r3a.x, r3a.x);
            h3[1] = fmaf(ax, r3b.x - r3a.y, r3a.y);
            h3[2] = fmaf(ax, r3b.y - r3b.x, r3b.x);

            // Masked vertical FMAs
#pragma unroll
            for (int q = 0; q < 3; q++) {
                acc[j][0 + q] = fmaf(wv1, h1[q], fmaf(wv0, h0[q], acc[j][0 + q]));
                acc[j][3 + q] = fmaf(wv1, h2[q], fmaf(wv0, h1[q], acc[j][3 + q]));
                acc[j][6 + q] = fmaf(wv1, h3[q], fmaf(wv0, h2[q], acc[j][6 + q]));
            }
        }
    }

    // Write 4 cells x 3x3 outputs (adjacent threads -> adjacent 3-float groups)
    float* ob = out + ((size_t)(b * CH + c)) * (HO * HO);
#pragma unroll
    for (int j = 0; j < 4; j++) {
        int cell = cell0 + t + 256 * j;
        int cy = cell >> 6;
        int cx = cell & 63;
#pragma unroll
        for (int i = 0; i < 3; i++) {
            float* row = ob + (size_t)(cy * 3 + i) * HO + cx * 3;
            row[0] = acc[j][i * 3 + 0];
            row[1] = acc[j][i * 3 + 1];
            row[2] = acc[j][i * 3 + 2];
        }
    }
}

extern "C" void kernel_launch(void* const* d_in, const int* in_sizes, int n_in,
                              void* d_out, int out_size) {
    const float* src   = (const float*)d_in[0];  // (16, 256, 64, 64)
    const float* flow  = (const float*)d_in[1];  // (16, 2, 64, 64)
    const float* masks = (const float*)d_in[2];  // (16, 1, 64, 64)
    float* out = (float*)d_out;                  // (4, 256, 192, 192)

    meta_kernel<<<(NBB * CELLS + 255) / 256, 256>>>(flow, masks);

    dim3 grid(CH, NB, 4);
    extract_kernel<<<grid, 256>>>(src, out);
}

// round 10
// speedup vs baseline: 1.6449x; 1.1066x over previous
#include <cuda_runtime.h>
#include <cuda_fp16.h>

// Problem constants
#define SRC_HW   64
#define CELLS    4096        // 64*64 flow cells per batch-slice
#define CH       256
#define NB       4           // output batches
#define NN       4           // accumulated slices (num)
#define HO       192         // output H = W = 3*64
#define NBB      16          // NB*NN batch-slices
#define PW       72          // padded plane width/height (4 zero border each side)
#define RW       36          // half2 words per padded row
#define REPW     (PW * RW)   // half2 words per parity replica (2592)

// Precomputed per-(bb, cell) metadata:
//  .x = bitcast int: BYTE offset of patch-row base into the half2 replica pair
//       (parity*REPW + py*RW + (px>>1)) * 4
//  .y = m * (1 - ay)
//  .z = m * ay
//  .w = ax
__device__ float4 g_meta[NBB * CELLS];   // 1 MB static scratch

__global__ void meta_kernel(const float* __restrict__ flow,
                            const float* __restrict__ masks) {
    int idx = blockIdx.x * blockDim.x + threadIdx.x;
    if (idx >= NBB * CELLS) return;
    int bb   = idx >> 12;
    int cell = idx & (CELLS - 1);
    int cy = cell >> 6;
    int cx = cell & 63;

    float fy = flow[((size_t)(bb * 2 + 0)) * CELLS + cell];
    float fx = flow[((size_t)(bb * 2 + 1)) * CELLS + cell];
    float m  = masks[(size_t)bb * CELLS + cell];

    float by = (float)cy + fy;
    float bx = (float)cx + fx;
    float y0f = floorf(by);
    float x0f = floorf(bx);
    float ay = by - y0f;
    float ax = bx - x0f;
    int y0 = (int)y0f;
    int x0 = (int)x0f;

    int yb = min(max(y0 - 1, -4), SRC_HW);
    int xb = min(max(x0 - 1, -4), SRC_HW);
    int py = yb + 4;                  // 0..68
    int px = xb + 4;                  // 0..68
    int parity = px & 1;
    int word   = px >> 1;             // 0..34
    int mo = (parity * REPW + py * RW + word) * 4;   // byte offset

    g_meta[idx] = make_float4(__int_as_float(mo), m * (1.0f - ay), m * ay, ax);
}

static __device__ __forceinline__ unsigned pack_h2(float a, float b) {
    __half2 h = __floats2half2_rn(a, b);
    return *reinterpret_cast<unsigned*>(&h);
}

// One block per (channel, batch, cell-quarter). Source plane prefetched into
// registers (LDG overlapped with previous gather), converted to fp16 and
// written to BOTH x-parity replicas directly from registers (shfl supplies
// the straddling neighbor half). Patch rows are 2 LDS.32 from the
// parity-matched replica.
__global__ __launch_bounds__(256, 3)
void extract_kernel(const float* __restrict__ src, float* __restrict__ out) {
    const int c = blockIdx.x;   // 0..255
    const int b = blockIdx.y;   // 0..3
    const int z = blockIdx.z;   // 0..3  (cell quarter)
    const int t = threadIdx.x;  // 0..255

    __shared__ __align__(16) unsigned rep[2 * REPW];   // 20736 B

    // Zero everything once (borders stay zero; interiors overwritten per n).
    {
        uint4 z4 = make_uint4(0u, 0u, 0u, 0u);
        uint4* rz = (uint4*)rep;
        for (int i = t; i < (2 * REPW) / 4; i += 256) rz[i] = z4;
    }

    float acc[4][9];
#pragma unroll
    for (int j = 0; j < 4; j++)
#pragma unroll
        for (int q = 0; q < 9; q++) acc[j][q] = 0.0f;

    const int cell0 = z * 1024;

    // Prefetch plane n=0
    float4 v[4];
    {
        const float4* sp = (const float4*)(src + ((size_t)(b * CH + c)) * CELLS);
#pragma unroll
        for (int k = 0; k < 4; k++) v[k] = sp[t + 256 * k];
    }

    for (int n = 0; n < NN; n++) {
        __syncthreads();   // previous gather (or zeroing) done before overwrite
        const int bb = n * NB + b;

        // Fill both replicas from registers.
        // Warp lanes cover consecutive float4s; each warp spans exactly 2
        // source rows, so the row-end lane (col4==15) has no in-row neighbor
        // and substitutes the zero border.
#pragma unroll
        for (int k = 0; k < 4; k++) {
            int i    = t + 256 * k;    // float4 index 0..1023
            int row  = i >> 4;         // 16 float4 per source row
            int col4 = i & 15;
            unsigned u0 = pack_h2(v[k].x, v[k].y);
            unsigned u1 = pack_h2(v[k].z, v[k].w);
            unsigned nb = __shfl_down_sync(0xffffffffu, u0, 1);
            if (col4 == 15) nb = 0u;

            int base = (row + 4) * RW + 2 + 2 * col4;   // even -> 8B aligned
            *(uint2*)&rep[base] = make_uint2(u0, u1);
            unsigned w0 = (u0 >> 16) | (u1 << 16);      // (h1,h2)
            unsigned w1 = (u1 >> 16) | (nb << 16);      // (h3,next h0)
            *(uint2*)&rep[REPW + base] = make_uint2(w0, w1);
            if (col4 == 0)   // boundary word (border0, h0) at m=1
                rep[REPW + (row + 4) * RW + 1] = (u0 & 0xFFFFu) << 16;
        }

        // Prefetch next plane while this one is gathered.
        if (n < NN - 1) {
            const float4* sp = (const float4*)(src +
                ((size_t)(((n + 1) * NB + b) * CH + c)) * CELLS);
#pragma unroll
            for (int k = 0; k < 4; k++) v[k] = sp[t + 256 * k];
        }
        __syncthreads();

        const float4* __restrict__ metaB = g_meta + (size_t)bb * CELLS + cell0;

#pragma unroll
        for (int j = 0; j < 4; j++) {
            float4 mt = metaB[t + 256 * j];
            const __half2* __restrict__ p =
                (const __half2*)((const char*)rep + __float_as_int(mt.x));
            float wv0 = mt.y, wv1 = mt.z, ax = mt.w;

            // 4x4 patch: 2 LDS.32 per row
            float2 r0a = __half22float2(p[0]);
            float2 r0b = __half22float2(p[1]);
            float2 r1a = __half22float2(p[RW]);
            float2 r1b = __half22float2(p[RW + 1]);
            float2 r2a = __half22float2(p[2 * RW]);
            float2 r2b = __half22float2(p[2 * RW + 1]);
            float2 r3a = __half22float2(p[3 * RW]);
            float2 r3b = __half22float2(p[3 * RW + 1]);

            // Horizontal lerps (v0..v3 = a.x, a.y, b.x, b.y)
            float h0[3], h1[3], h2[3], h3[3];
            h0[0] = fmaf(ax, r0a.y - r0a.x, r0a.x);
            h0[1] = fmaf(ax, r0b.x - r0a.y, r0a.y);
            h0[2] = fmaf(ax, r0b.y - r0b.x, r0b.x);
            h1[0] = fmaf(ax, r1a.y - r1a.x, r1a.x);
            h1[1] = fmaf(ax, r1b.x - r1a.y, r1a.y);
            h1[2] = fmaf(ax, r1b.y - r1b.x, r1b.x);
            h2[0] = fmaf(ax, r2a.y - r2a.x, r2a.x);
            h2[1] = fmaf(ax, r2b.x - r2a.y, r2a.y);
            h2[2] = fmaf(ax, r2b.y - r2b.x, r2b.x);
            h3[0] = fmaf(ax, r3a.y - r3a.x, r3a.x);
            h3[1] = fmaf(ax, r3b.x - r3a.y, r3a.y);
            h3[2] = fmaf(ax, r3b.y - r3b.x, r3b.x);

            // Masked vertical FMAs
#pragma unroll
            for (int q = 0; q < 3; q++) {
                acc[j][0 + q] = fmaf(wv1, h1[q], fmaf(wv0, h0[q], acc[j][0 + q]));
                acc[j][3 + q] = fmaf(wv1, h2[q], fmaf(wv0, h1[q], acc[j][3 + q]));
                acc[j][6 + q] = fmaf(wv1, h3[q], fmaf(wv0, h2[q], acc[j][6 + q]));
            }
        }
    }

    // Write 4 cells x 3x3 outputs (adjacent threads -> adjacent 3-float groups)
    float* ob = out + ((size_t)(b * CH + c)) * (HO * HO);
#pragma unroll
    for (int j = 0; j < 4; j++) {
        int cell = cell0 + t + 256 * j;
        int cy = cell >> 6;
        int cx = cell & 63;
#pragma unroll
        for (int i = 0; i < 3; i++) {
            float* row = ob + (size_t)(cy * 3 + i) * HO + cx * 3;
            row[0] = acc[j][i * 3 + 0];
            row[1] = acc[j][i * 3 + 1];
            row[2] = acc[j][i * 3 + 2];
        }
    }
}

extern "C" void kernel_launch(void* const* d_in, const int* in_sizes, int n_in,
                              void* d_out, int out_size) {
    const float* src   = (const float*)d_in[0];  // (16, 256, 64, 64)
    const float* flow  = (const float*)d_in[1];  // (16, 2, 64, 64)
    const float* masks = (const float*)d_in[2];  // (16, 1, 64, 64)
    float* out = (float*)d_out;                  // (4, 256, 192, 192)

    meta_kernel<<<(NBB * CELLS + 255) / 256, 256>>>(flow, masks);

    dim3 grid(CH, NB, 4);
    extract_kernel<<<grid, 256>>>(src, out);
}